// round 7
// baseline (speedup 1.0000x reference)
#include <cuda_runtime.h>
#include <cstdint>

#define NF 40
#define NP 780        // 40*39/2
#define ED 64
#define AS 32
#define THREADS 256
#define CP 128        // pairs per chunk
#define NCH 7
#define NPAD (NCH*CP) // 896

#define WP 40         // W tile pitch (40 % 32 == 8 -> conflict-free frag loads)

// ---- dynamic smem byte offsets ----
#define FB_OFF    0        // IP big frags  [8kt][4mgrp][2mt][32lane] uint4 = 32768
#define FR_OFF    32768    // IP res frags                              32768
#define WB_OFF    65536    // W big   [64][40] f32                      10240
#define WR_OFF    75776    // W res   [64][40] f32                      10240
#define XS_OFF    86016    // xs [40][65] f32                           10400
#define OFFS_OFF  96416    // [896] u32                                  3584
#define LOG_OFF   100000   // [896] f32                                  3584
#define PART_OFF  103584   // [128][2] f32                               1024
#define AB_OFF    104608   // 32 f32
#define PW_OFF    104736   // 32 f32
#define FW_OFF    104864   // 64 f32
#define RMAX_OFF  105120   // 8 f32
#define RSUM_OFF  105152   // 8 f32
#define RED_OFF   105184   // 64 f32
#define SMEM_TOTAL 105440  // x2 CTAs fits 228KB/SM

__device__ __forceinline__ uint32_t tf32_of(float v) {
    uint32_t r; asm("cvt.rna.tf32.f32 %0, %1;" : "=r"(r) : "f"(v)); return r;
}

__device__ __forceinline__ void mma8(float& c0, float& c1, float& c2, float& c3,
                                     uint32_t a0, uint32_t a1, uint32_t a2, uint32_t a3,
                                     uint32_t b0, uint32_t b1) {
    asm("mma.sync.aligned.m16n8k8.row.col.f32.tf32.tf32.f32 "
        "{%0,%1,%2,%3}, {%4,%5,%6,%7}, {%8,%9}, {%0,%1,%2,%3};"
        : "+f"(c0), "+f"(c1), "+f"(c2), "+f"(c3)
        : "r"(a0), "r"(a1), "r"(a2), "r"(a3), "r"(b0), "r"(b1));
}

__global__ __launch_bounds__(THREADS, 2) void afm_kernel(
    const float* __restrict__ x,
    const float* __restrict__ attn_w,
    const float* __restrict__ attn_b,
    const float* __restrict__ proj_w,
    const float* __restrict__ proj_b,
    const float* __restrict__ fc_w,
    const float* __restrict__ fc_b,
    float* __restrict__ out)
{
    extern __shared__ char smem[];
    float* xs        = (float*)(smem + XS_OFF);
    float* logits_s  = (float*)(smem + LOG_OFF);
    float* part      = (float*)(smem + PART_OFF);
    float* ab_s      = (float*)(smem + AB_OFF);
    float* pw_s      = (float*)(smem + PW_OFF);
    float* fw_s      = (float*)(smem + FW_OFF);
    float* rmax      = (float*)(smem + RMAX_OFF);
    float* rsum      = (float*)(smem + RSUM_OFF);
    float* red_s     = (float*)(smem + RED_OFF);
    uint32_t* offs   = (uint32_t*)(smem + OFFS_OFF);
    uint32_t* WBu    = (uint32_t*)(smem + WB_OFF);
    uint32_t* WRu    = (uint32_t*)(smem + WR_OFF);

    const int tid  = threadIdx.x;
    const int lane = tid & 31;
    const int wid  = tid >> 5;
    const int b    = blockIdx.x;

    // ---- Phase 1: stage inputs ----
    const float* xb = x + (long long)b * (NF * ED);
    for (int idx = tid; idx < NF * ED; idx += THREADS)
        xs[(idx >> 6) * 65 + (idx & 63)] = xb[idx];

    // W big/res tf32 tiles [d][40]
    for (int e = tid; e < ED * AS; e += THREADS) {
        int d = e >> 5, n = e & 31;
        float w = attn_w[e];
        uint32_t big = tf32_of(w);
        uint32_t res = tf32_of(w - __uint_as_float(big));
        WBu[d * WP + n] = big;
        WRu[d * WP + n] = res;
    }

    if (tid < AS) { pw_s[tid] = proj_w[tid]; ab_s[tid] = attn_b[tid]; }
    if (tid < ED) fw_s[tid] = fc_w[tid];

    // packed xs byte-offsets per pair (dead pairs -> (0,0); produce zeros, never used)
    for (int p = tid; p < NPAD; p += THREADS) {
        uint32_t o = 0;
        if (p < NP) {
            int i = 0, rem = p;
            while (rem >= NF - 1 - i) { rem -= NF - 1 - i; ++i; }
            int j = i + 1 + rem;
            o = (uint32_t)(i * 260) | ((uint32_t)(j * 260) << 16);
        }
        offs[p] = o;
    }
    const float pb = proj_b[0];
    __syncthreads();

    const int kd   = lane & 3;        // threadID_in_group
    const int qr   = lane >> 2;       // groupID
    const int mgrp = wid & 3;         // 4 M-groups x 32 pairs
    const int ngrp = wid >> 2;        // 2 N-groups x 16 cols

    // ---- hoist B fragments (W) into registers: invariant across chunks ----
    uint32_t Bb[8][2][2], Br[8][2][2];
#pragma unroll
    for (int kt = 0; kt < 8; ++kt) {
#pragma unroll
        for (int nt = 0; nt < 2; ++nt) {
            const int nc = ngrp * 16 + nt * 8 + qr;
            Bb[kt][nt][0] = WBu[(kt * 8 + kd) * WP + nc];
            Bb[kt][nt][1] = WBu[(kt * 8 + kd + 4) * WP + nc];
            Br[kt][nt][0] = WRu[(kt * 8 + kd) * WP + nc];
            Br[kt][nt][1] = WRu[(kt * 8 + kd + 4) * WP + nc];
        }
    }

    const char* xsc = (const char*)xs;

    // frag byte offset for this thread (gemm side, mt=0): kt*4096 + (mgrp*2+mt)*512 + lane*16
    const uint32_t gA = (uint32_t)((mgrp * 2) * 512 + lane * 16);

    // ---- Phase 2: chunked 3xtf32 MMA GEMM ----
    for (int t = 0; t < NCH; ++t) {
        const int cbase = t * CP;

        // ---- build: thread owns (p, p+8) x (d0, d0+4), emits one frag quad per kt ----
        {
            const int plocal = mgrp * 32 + (wid >> 2) * 16 + qr;   // wid>>2 = mt role in build
            const uint32_t o1 = offs[cbase + plocal];
            const uint32_t o2 = offs[cbase + plocal + 8];
            const char* xi1 = xsc + (o1 & 0xffffu);
            const char* xj1 = xsc + (o1 >> 16);
            const char* xi2 = xsc + (o2 & 0xffffu);
            const char* xj2 = xsc + (o2 >> 16);
            const uint32_t fB = (uint32_t)((mgrp * 2 + (wid >> 2)) * 512 + lane * 16);
#pragma unroll
            for (int kt = 0; kt < 8; ++kt) {
                const int d0 = (kt * 8 + kd) * 4;
                const int d1 = d0 + 16;
                float v0 = *(const float*)(xi1 + d0) * *(const float*)(xj1 + d0);
                float v1 = *(const float*)(xi2 + d0) * *(const float*)(xj2 + d0);
                float v2 = *(const float*)(xi1 + d1) * *(const float*)(xj1 + d1);
                float v3 = *(const float*)(xi2 + d1) * *(const float*)(xj2 + d1);
                uint4 big, res;
                big.x = tf32_of(v0); res.x = tf32_of(v0 - __uint_as_float(big.x));
                big.y = tf32_of(v1); res.y = tf32_of(v1 - __uint_as_float(big.y));
                big.z = tf32_of(v2); res.z = tf32_of(v2 - __uint_as_float(big.z));
                big.w = tf32_of(v3); res.w = tf32_of(v3 - __uint_as_float(big.w));
                *(uint4*)(smem + FB_OFF + fB + kt * 4096) = big;
                *(uint4*)(smem + FR_OFF + fB + kt * 4096) = res;
            }
        }
        __syncthreads();

        // ---- accumulators init with bias ----
        float acc[2][2][4];
#pragma unroll
        for (int mt = 0; mt < 2; ++mt)
#pragma unroll
            for (int nt = 0; nt < 2; ++nt) {
                const int c0 = ngrp * 16 + nt * 8 + kd * 2;
                acc[mt][nt][0] = ab_s[c0];
                acc[mt][nt][1] = ab_s[c0 + 1];
                acc[mt][nt][2] = ab_s[c0];
                acc[mt][nt][3] = ab_s[c0 + 1];
            }

        // ---- K loop: frag quads via LDS.128, constant-offset addressing ----
#pragma unroll
        for (int kt = 0; kt < 8; ++kt) {
#pragma unroll
            for (int mt = 0; mt < 2; ++mt) {
                const uint32_t ao = gA + (uint32_t)(kt * 4096 + mt * 512);
                const uint4 A = *(const uint4*)(smem + FB_OFF + ao);
                const uint4 R = *(const uint4*)(smem + FR_OFF + ao);
#pragma unroll
                for (int nt = 0; nt < 2; ++nt) {
                    mma8(acc[mt][nt][0], acc[mt][nt][1], acc[mt][nt][2], acc[mt][nt][3],
                         A.x, A.y, A.z, A.w, Bb[kt][nt][0], Bb[kt][nt][1]);
                    mma8(acc[mt][nt][0], acc[mt][nt][1], acc[mt][nt][2], acc[mt][nt][3],
                         A.x, A.y, A.z, A.w, Br[kt][nt][0], Br[kt][nt][1]);
                    mma8(acc[mt][nt][0], acc[mt][nt][1], acc[mt][nt][2], acc[mt][nt][3],
                         R.x, R.y, R.z, R.w, Bb[kt][nt][0], Bb[kt][nt][1]);
                }
            }
        }

        // ---- epilogue: relu + proj, reduce 16 cols, quad-reduce lanes ----
#pragma unroll
        for (int mt = 0; mt < 2; ++mt) {
            float lp0 = 0.f, lp1 = 0.f;
#pragma unroll
            for (int nt = 0; nt < 2; ++nt) {
                const int c0 = ngrp * 16 + nt * 8 + kd * 2;
                lp0 += fmaxf(acc[mt][nt][0], 0.f) * pw_s[c0] + fmaxf(acc[mt][nt][1], 0.f) * pw_s[c0 + 1];
                lp1 += fmaxf(acc[mt][nt][2], 0.f) * pw_s[c0] + fmaxf(acc[mt][nt][3], 0.f) * pw_s[c0 + 1];
            }
            lp0 += __shfl_xor_sync(0xffffffffu, lp0, 1);
            lp0 += __shfl_xor_sync(0xffffffffu, lp0, 2);
            lp1 += __shfl_xor_sync(0xffffffffu, lp1, 1);
            lp1 += __shfl_xor_sync(0xffffffffu, lp1, 2);
            if (kd == 0) {
                const int p0 = mgrp * 32 + mt * 16 + qr;
                part[p0 * 2 + ngrp]       = lp0;
                part[(p0 + 8) * 2 + ngrp] = lp1;
            }
        }
        __syncthreads();

        if (tid < CP) {
            const int p = cbase + tid;
            if (p < NP) logits_s[p] = part[tid * 2] + part[tid * 2 + 1] + pb;
        }
        // next chunk's build sync orders the part[] reuse
    }
    __syncthreads();

    // ---- Phase 3: softmax over 780 (unnormalized; fold 1/S at end) ----
    float lm = -3.4e38f;
    for (int p = tid; p < NP; p += THREADS) lm = fmaxf(lm, logits_s[p]);
#pragma unroll
    for (int o = 16; o > 0; o >>= 1) lm = fmaxf(lm, __shfl_xor_sync(0xffffffffu, lm, o));
    if (lane == 0) rmax[wid] = lm;
    __syncthreads();

    float gmax = rmax[0];
#pragma unroll
    for (int wq = 1; wq < 8; ++wq) gmax = fmaxf(gmax, rmax[wq]);

    float ls = 0.f;
    for (int p = tid; p < NP; p += THREADS) {
        float e = __expf(logits_s[p] - gmax);
        logits_s[p] = e;
        ls += e;
    }
#pragma unroll
    for (int o = 16; o > 0; o >>= 1) ls += __shfl_xor_sync(0xffffffffu, ls, o);
    if (lane == 0) rsum[wid] = ls;
    __syncthreads();

    // ---- Phase 4: weighted sum over pairs (recompute ip), fc dot ----
    float* part4 = (float*)(smem + FB_OFF);   // frag tiles dead; 8 warps x 64 dims
    float accL = 0.f, accH = 0.f;
    for (int p = wid; p < NP; p += 8) {
        const float s = logits_s[p];
        const uint32_t o = offs[p];
        const char* xi = xsc + (o & 0xffffu);
        const char* xj = xsc + (o >> 16);
        accL += s * (*(const float*)(xi + lane * 4)       * *(const float*)(xj + lane * 4));
        accH += s * (*(const float*)(xi + 128 + lane * 4) * *(const float*)(xj + 128 + lane * 4));
    }
    part4[wid * 64 + lane]      = accL;
    part4[wid * 64 + 32 + lane] = accH;
    __syncthreads();

    if (tid < 64) {
        float v = 0.f;
#pragma unroll
        for (int wq = 0; wq < 8; ++wq) v += part4[wq * 64 + tid];
        red_s[tid] = v * fw_s[tid];
    }
    __syncthreads();

    if (tid == 0) {
        float S = 0.f;
#pragma unroll
        for (int wq = 0; wq < 8; ++wq) S += rsum[wq];
        float tt = 0.f;
#pragma unroll
        for (int k = 0; k < 64; ++k) tt += red_s[k];
        out[b] = tt / S + fc_b[0];
    }
}

extern "C" void kernel_launch(void* const* d_in, const int* in_sizes, int n_in,
                              void* d_out, int out_size)
{
    const float* x      = (const float*)d_in[0];
    const float* attn_w = (const float*)d_in[1];
    const float* attn_b = (const float*)d_in[2];
    const float* proj_w = (const float*)d_in[3];
    const float* proj_b = (const float*)d_in[4];
    const float* fc_w   = (const float*)d_in[5];
    const float* fc_b   = (const float*)d_in[6];
    float* out = (float*)d_out;

    cudaFuncSetAttribute(afm_kernel, cudaFuncAttributeMaxDynamicSharedMemorySize, SMEM_TOTAL);
    afm_kernel<<<2048, THREADS, SMEM_TOTAL>>>(x, attn_w, attn_b, proj_w, proj_b, fc_w, fc_b, out);
}

// round 8
// speedup vs baseline: 1.3499x; 1.3499x over previous
#include <cuda_runtime.h>
#include <cstdint>

#define NF 40
#define NP 780        // 40*39/2
#define ED 64
#define AS 32
#define THREADS 256
#define CP 128        // pairs per chunk
#define NCH 7
#define NPAD (NCH*CP) // 896

#define PP 136        // IP tile pitch in f32 words (136 % 32 == 8 -> conflict-free frags)
#define WP 40         // W tile pitch  (40 % 32 == 8)

// ---- dynamic smem byte offsets ----
#define IPB_OFF   0        // IP big  [64][136] f32  34816
#define WB_OFF    34816    // W big   [64][40]  f32  10240
#define WR_OFF    45056    // W res   [64][40]  f32  10240
#define XS_OFF    55296    // xs [40][65] f32        10400
#define OFFS_OFF  65696    // [896] u32               3584
#define LOG_OFF   69280    // [896] f32               3584
#define PART_OFF  72864    // [128][2] f32            1024
#define AB_OFF    73888    // 32 f32
#define PW_OFF    74016    // 32 f32
#define FW_OFF    74144    // 64 f32
#define RMAX_OFF  74400    // 8 f32
#define RSUM_OFF  74432    // 8 f32
#define RED_OFF   74464    // 64 f32
#define SMEM_TOTAL 74720   // x3 CTAs = 224160, may fit 228KB/SM; worst case 2 CTAs

__device__ __forceinline__ uint32_t tf32_of(float v) {
    uint32_t r; asm("cvt.rna.tf32.f32 %0, %1;" : "=r"(r) : "f"(v)); return r;
}

__device__ __forceinline__ void mma8(float& c0, float& c1, float& c2, float& c3,
                                     uint32_t a0, uint32_t a1, uint32_t a2, uint32_t a3,
                                     uint32_t b0, uint32_t b1) {
    asm("mma.sync.aligned.m16n8k8.row.col.f32.tf32.tf32.f32 "
        "{%0,%1,%2,%3}, {%4,%5,%6,%7}, {%8,%9}, {%0,%1,%2,%3};"
        : "+f"(c0), "+f"(c1), "+f"(c2), "+f"(c3)
        : "r"(a0), "r"(a1), "r"(a2), "r"(a3), "r"(b0), "r"(b1));
}

__global__ __launch_bounds__(THREADS, 2) void afm_kernel(
    const float* __restrict__ x,
    const float* __restrict__ attn_w,
    const float* __restrict__ attn_b,
    const float* __restrict__ proj_w,
    const float* __restrict__ proj_b,
    const float* __restrict__ fc_w,
    const float* __restrict__ fc_b,
    float* __restrict__ out)
{
    extern __shared__ char smem[];
    float* xs        = (float*)(smem + XS_OFF);
    float* logits_s  = (float*)(smem + LOG_OFF);
    float* part      = (float*)(smem + PART_OFF);
    float* ab_s      = (float*)(smem + AB_OFF);
    float* pw_s      = (float*)(smem + PW_OFF);
    float* fw_s      = (float*)(smem + FW_OFF);
    float* rmax      = (float*)(smem + RMAX_OFF);
    float* rsum      = (float*)(smem + RSUM_OFF);
    float* red_s     = (float*)(smem + RED_OFF);
    uint32_t* offs   = (uint32_t*)(smem + OFFS_OFF);
    uint32_t* IPBu   = (uint32_t*)(smem + IPB_OFF);
    uint32_t* WBu    = (uint32_t*)(smem + WB_OFF);
    uint32_t* WRu    = (uint32_t*)(smem + WR_OFF);

    const int tid  = threadIdx.x;
    const int lane = tid & 31;
    const int wid  = tid >> 5;
    const int b    = blockIdx.x;

    // ---- Phase 1: stage inputs ----
    const float* xb = x + (long long)b * (NF * ED);
    for (int idx = tid; idx < NF * ED; idx += THREADS)
        xs[(idx >> 6) * 65 + (idx & 63)] = xb[idx];

    // W big/res tf32 tiles [d][40]  (W keeps full 2-term precision; it's free)
    for (int e = tid; e < ED * AS; e += THREADS) {
        int d = e >> 5, n = e & 31;
        float w = attn_w[e];
        uint32_t big = tf32_of(w);
        uint32_t res = tf32_of(w - __uint_as_float(big));
        WBu[d * WP + n] = big;
        WRu[d * WP + n] = res;
    }

    if (tid < AS) { pw_s[tid] = proj_w[tid]; ab_s[tid] = attn_b[tid]; }
    if (tid < ED) fw_s[tid] = fc_w[tid];

    // packed xs byte-offsets per pair (dead pairs -> (0,0): zero rows, never consumed)
    for (int p = tid; p < NPAD; p += THREADS) {
        uint32_t o = 0;
        if (p < NP) {
            int i = 0, rem = p;
            while (rem >= NF - 1 - i) { rem -= NF - 1 - i; ++i; }
            int j = i + 1 + rem;
            o = (uint32_t)(i * 260) | ((uint32_t)(j * 260) << 16);
        }
        offs[p] = o;
    }
    const float pb = proj_b[0];
    __syncthreads();

    const int kd   = lane & 3;        // threadID_in_group
    const int qr   = lane >> 2;       // groupID
    const int mgrp = wid & 3;         // 4 M-groups x 32 pairs
    const int ngrp = wid >> 2;        // 2 N-groups x 16 cols

    // ---- hoist B fragments (W big + res) into registers: chunk-invariant ----
    uint32_t Bb[8][2][2], Br[8][2][2];
#pragma unroll
    for (int kt = 0; kt < 8; ++kt) {
#pragma unroll
        for (int nt = 0; nt < 2; ++nt) {
            const int nc = ngrp * 16 + nt * 8 + qr;
            Bb[kt][nt][0] = WBu[(kt * 8 + kd) * WP + nc];
            Bb[kt][nt][1] = WBu[(kt * 8 + kd + 4) * WP + nc];
            Br[kt][nt][0] = WRu[(kt * 8 + kd) * WP + nc];
            Br[kt][nt][1] = WRu[(kt * 8 + kd + 4) * WP + nc];
        }
    }

    const uint4* offs4 = (const uint4*)(smem + OFFS_OFF);
    const char* xsc = (const char*)xs;
    const int pg = lane;

    // ---- Phase 2: chunked MMA GEMM, A = tf32(IP), W = big+res ----
    for (int t = 0; t < NCH; ++t) {
        const int cbase = t * CP;

        // build IP big tile [d][pitch 136] (no residual tile)
        {
            const uint4 oo = offs4[t * 32 + pg];
#pragma unroll
            for (int it = 0; it < 8; ++it) {
                const int d = wid + it * 8;
                const char* xsd = xsc + d * 4;
                float vx = *(const float*)(xsd + (oo.x & 0xffffu)) * *(const float*)(xsd + (oo.x >> 16));
                float vy = *(const float*)(xsd + (oo.y & 0xffffu)) * *(const float*)(xsd + (oo.y >> 16));
                float vz = *(const float*)(xsd + (oo.z & 0xffffu)) * *(const float*)(xsd + (oo.z >> 16));
                float vw = *(const float*)(xsd + (oo.w & 0xffffu)) * *(const float*)(xsd + (oo.w >> 16));
                uint4 big;
                big.x = tf32_of(vx);
                big.y = tf32_of(vy);
                big.z = tf32_of(vz);
                big.w = tf32_of(vw);
                *(uint4*)(IPBu + d * PP + pg * 4) = big;
            }
        }
        __syncthreads();

        // accumulators init with bias
        float acc[2][2][4];
#pragma unroll
        for (int mt = 0; mt < 2; ++mt)
#pragma unroll
            for (int nt = 0; nt < 2; ++nt) {
                const int c0 = ngrp * 16 + nt * 8 + kd * 2;
                acc[mt][nt][0] = ab_s[c0];
                acc[mt][nt][1] = ab_s[c0 + 1];
                acc[mt][nt][2] = ab_s[c0];
                acc[mt][nt][3] = ab_s[c0 + 1];
            }

        // K loop: 8 kt x 2 mt x 2 nt x 2 mma (bigA*bigW + bigA*resW)
#pragma unroll
        for (int kt = 0; kt < 8; ++kt) {
#pragma unroll
            for (int mt = 0; mt < 2; ++mt) {
                const int pr = mgrp * 32 + mt * 16 + qr;
                const uint32_t* rb0 = IPBu + (kt * 8 + kd) * PP + pr;
                const uint32_t* rb1 = IPBu + (kt * 8 + kd + 4) * PP + pr;
                uint32_t a0 = rb0[0], a1 = rb0[8], a2 = rb1[0], a3 = rb1[8];
#pragma unroll
                for (int nt = 0; nt < 2; ++nt) {
                    mma8(acc[mt][nt][0], acc[mt][nt][1], acc[mt][nt][2], acc[mt][nt][3],
                         a0, a1, a2, a3, Bb[kt][nt][0], Bb[kt][nt][1]);
                    mma8(acc[mt][nt][0], acc[mt][nt][1], acc[mt][nt][2], acc[mt][nt][3],
                         a0, a1, a2, a3, Br[kt][nt][0], Br[kt][nt][1]);
                }
            }
        }

        // epilogue: relu + proj, reduce over warp's 16 cols, quad-reduce lanes
#pragma unroll
        for (int mt = 0; mt < 2; ++mt) {
            float lp0 = 0.f, lp1 = 0.f;
#pragma unroll
            for (int nt = 0; nt < 2; ++nt) {
                const int c0 = ngrp * 16 + nt * 8 + kd * 2;
                lp0 += fmaxf(acc[mt][nt][0], 0.f) * pw_s[c0] + fmaxf(acc[mt][nt][1], 0.f) * pw_s[c0 + 1];
                lp1 += fmaxf(acc[mt][nt][2], 0.f) * pw_s[c0] + fmaxf(acc[mt][nt][3], 0.f) * pw_s[c0 + 1];
            }
            lp0 += __shfl_xor_sync(0xffffffffu, lp0, 1);
            lp0 += __shfl_xor_sync(0xffffffffu, lp0, 2);
            lp1 += __shfl_xor_sync(0xffffffffu, lp1, 1);
            lp1 += __shfl_xor_sync(0xffffffffu, lp1, 2);
            if (kd == 0) {
                const int p0 = mgrp * 32 + mt * 16 + qr;
                part[p0 * 2 + ngrp]       = lp0;
                part[(p0 + 8) * 2 + ngrp] = lp1;
            }
        }
        __syncthreads();

        if (tid < CP) {
            const int p = cbase + tid;
            if (p < NP) logits_s[p] = part[tid * 2] + part[tid * 2 + 1] + pb;
        }
        // next chunk's build sync orders the part[] reuse
    }
    __syncthreads();

    // ---- Phase 3: softmax over 780 (unnormalized; fold 1/S at end) ----
    float lm = -3.4e38f;
    for (int p = tid; p < NP; p += THREADS) lm = fmaxf(lm, logits_s[p]);
#pragma unroll
    for (int o = 16; o > 0; o >>= 1) lm = fmaxf(lm, __shfl_xor_sync(0xffffffffu, lm, o));
    if (lane == 0) rmax[wid] = lm;
    __syncthreads();

    float gmax = rmax[0];
#pragma unroll
    for (int wq = 1; wq < 8; ++wq) gmax = fmaxf(gmax, rmax[wq]);

    float ls = 0.f;
    for (int p = tid; p < NP; p += THREADS) {
        float e = __expf(logits_s[p] - gmax);
        logits_s[p] = e;
        ls += e;
    }
#pragma unroll
    for (int o = 16; o > 0; o >>= 1) ls += __shfl_xor_sync(0xffffffffu, ls, o);
    if (lane == 0) rsum[wid] = ls;
    __syncthreads();

    // ---- Phase 4: weighted sum over pairs (recompute ip), fc dot ----
    float* part4 = (float*)(smem + IPB_OFF);   // IP tile dead; 8 warps x 64 dims
    float accL = 0.f, accH = 0.f;
    for (int p = wid; p < NP; p += 8) {
        const float s = logits_s[p];
        const uint32_t o = offs[p];
        const char* xi = xsc + (o & 0xffffu);
        const char* xj = xsc + (o >> 16);
        accL += s * (*(const float*)(xi + lane * 4)       * *(const float*)(xj + lane * 4));
        accH += s * (*(const float*)(xi + 128 + lane * 4) * *(const float*)(xj + 128 + lane * 4));
    }
    part4[wid * 64 + lane]      = accL;
    part4[wid * 64 + 32 + lane] = accH;
    __syncthreads();

    if (tid < 64) {
        float v = 0.f;
#pragma unroll
        for (int wq = 0; wq < 8; ++wq) v += part4[wq * 64 + tid];
        red_s[tid] = v * fw_s[tid];
    }
    __syncthreads();

    if (tid == 0) {
        float S = 0.f;
#pragma unroll
        for (int wq = 0; wq < 8; ++wq) S += rsum[wq];
        float tt = 0.f;
#pragma unroll
        for (int k = 0; k < 64; ++k) tt += red_s[k];
        out[b] = tt / S + fc_b[0];
    }
}

extern "C" void kernel_launch(void* const* d_in, const int* in_sizes, int n_in,
                              void* d_out, int out_size)
{
    const float* x      = (const float*)d_in[0];
    const float* attn_w = (const float*)d_in[1];
    const float* attn_b = (const float*)d_in[2];
    const float* proj_w = (const float*)d_in[3];
    const float* proj_b = (const float*)d_in[4];
    const float* fc_w   = (const float*)d_in[5];
    const float* fc_b   = (const float*)d_in[6];
    float* out = (float*)d_out;

    cudaFuncSetAttribute(afm_kernel, cudaFuncAttributeMaxDynamicSharedMemorySize, SMEM_TOTAL);
    afm_kernel<<<2048, THREADS, SMEM_TOTAL>>>(x, attn_w, attn_b, proj_w, proj_b, fc_w, fc_b, out);
}

// round 9
// speedup vs baseline: 1.6727x; 1.2391x over previous
#include <cuda_runtime.h>
#include <cstdint>

#define NF 40
#define NP 780        // 40*39/2
#define ED 64
#define AS 32
#define THREADS 256
#define CP 128        // pairs per chunk
#define NCH 7
#define NPAD (NCH*CP) // 896

#define PP 136        // IP tile pitch in f32 words (136 % 32 == 8 -> conflict-free frags)
#define WP 40         // W tile pitch  (40 % 32 == 8)

// ---- dynamic smem byte offsets ----
#define IPB_OFF   0        // IP big  [64][136] f32  34816
#define WB_OFF    34816    // W big   [64][40]  f32  10240
#define XS_OFF    45056    // xs [40][65] f32        10400
#define OFFS_OFF  55456    // [896] u32               3584
#define PART_OFF  59040    // [896][2] f32            7168
#define LOG_OFF   66208    // [896] f32               3584
#define AB_OFF    69792    // 32 f32
#define PW_OFF    69920    // 32 f32
#define FW_OFF    70048    // 64 f32
#define RMAX_OFF  70304    // 8 f32
#define RSUM_OFF  70336    // 8 f32
#define RED_OFF   70368    // 64 f32
#define SMEM_TOTAL 70656   // x3 CTAs = 211968 <= 228KB/SM

__device__ __forceinline__ uint32_t tf32_of(float v) {
    uint32_t r; asm("cvt.rna.tf32.f32 %0, %1;" : "=r"(r) : "f"(v)); return r;
}

__device__ __forceinline__ void mma8(float& c0, float& c1, float& c2, float& c3,
                                     uint32_t a0, uint32_t a1, uint32_t a2, uint32_t a3,
                                     uint32_t b0, uint32_t b1) {
    asm("mma.sync.aligned.m16n8k8.row.col.f32.tf32.tf32.f32 "
        "{%0,%1,%2,%3}, {%4,%5,%6,%7}, {%8,%9}, {%0,%1,%2,%3};"
        : "+f"(c0), "+f"(c1), "+f"(c2), "+f"(c3)
        : "r"(a0), "r"(a1), "r"(a2), "r"(a3), "r"(b0), "r"(b1));
}

__global__ __launch_bounds__(THREADS, 3) void afm_kernel(
    const float* __restrict__ x,
    const float* __restrict__ attn_w,
    const float* __restrict__ attn_b,
    const float* __restrict__ proj_w,
    const float* __restrict__ proj_b,
    const float* __restrict__ fc_w,
    const float* __restrict__ fc_b,
    float* __restrict__ out)
{
    extern __shared__ char smem[];
    float* xs        = (float*)(smem + XS_OFF);
    float* logits_s  = (float*)(smem + LOG_OFF);
    float* part      = (float*)(smem + PART_OFF);   // [896][2]
    float* ab_s      = (float*)(smem + AB_OFF);
    float* pw_s      = (float*)(smem + PW_OFF);
    float* fw_s      = (float*)(smem + FW_OFF);
    float* rmax      = (float*)(smem + RMAX_OFF);
    float* rsum      = (float*)(smem + RSUM_OFF);
    float* red_s     = (float*)(smem + RED_OFF);
    uint32_t* offs   = (uint32_t*)(smem + OFFS_OFF);
    uint32_t* IPBu   = (uint32_t*)(smem + IPB_OFF);
    uint32_t* WBu    = (uint32_t*)(smem + WB_OFF);

    const int tid  = threadIdx.x;
    const int lane = tid & 31;
    const int wid  = tid >> 5;
    const int b    = blockIdx.x;

    // ---- Phase 1: stage inputs ----
    const float* xb = x + (long long)b * (NF * ED);
    for (int idx = tid; idx < NF * ED; idx += THREADS)
        xs[(idx >> 6) * 65 + (idx & 63)] = xb[idx];

    // W tf32 tile [d][40] (pure tf32: no residual)
    for (int e = tid; e < ED * AS; e += THREADS) {
        int d = e >> 5, n = e & 31;
        WBu[d * WP + n] = tf32_of(attn_w[e]);
    }

    if (tid < AS) { pw_s[tid] = proj_w[tid]; ab_s[tid] = attn_b[tid]; }
    if (tid < ED) fw_s[tid] = fc_w[tid];

    // packed xs byte-offsets per pair (dead pairs -> (0,0): zero rows, masked later)
    for (int p = tid; p < NPAD; p += THREADS) {
        uint32_t o = 0;
        if (p < NP) {
            int i = 0, rem = p;
            while (rem >= NF - 1 - i) { rem -= NF - 1 - i; ++i; }
            int j = i + 1 + rem;
            o = (uint32_t)(i * 260) | ((uint32_t)(j * 260) << 16);
        }
        offs[p] = o;
    }
    const float pb = proj_b[0];
    __syncthreads();

    const int kd   = lane & 3;        // threadID_in_group
    const int qr   = lane >> 2;       // groupID
    const int mgrp = wid & 3;         // 4 M-groups x 32 pairs
    const int ngrp = wid >> 2;        // 2 N-groups x 16 cols

    // ---- hoist B fragments (W) into registers: chunk-invariant, 32 regs ----
    uint32_t Bb[8][2][2];
#pragma unroll
    for (int kt = 0; kt < 8; ++kt) {
#pragma unroll
        for (int nt = 0; nt < 2; ++nt) {
            const int nc = ngrp * 16 + nt * 8 + qr;
            Bb[kt][nt][0] = WBu[(kt * 8 + kd) * WP + nc];
            Bb[kt][nt][1] = WBu[(kt * 8 + kd + 4) * WP + nc];
        }
    }

    const uint4* offs4 = (const uint4*)(smem + OFFS_OFF);
    const char* xsc = (const char*)xs;
    const int pg = lane;

    // ---- Phase 2: chunked pure-tf32 MMA GEMM ----
    for (int t = 0; t < NCH; ++t) {
        const int cbase = t * CP;

        // build IP tf32 tile [d][pitch 136]
        {
            const uint4 oo = offs4[t * 32 + pg];
#pragma unroll
            for (int it = 0; it < 8; ++it) {
                const int d = wid + it * 8;
                const char* xsd = xsc + d * 4;
                float vx = *(const float*)(xsd + (oo.x & 0xffffu)) * *(const float*)(xsd + (oo.x >> 16));
                float vy = *(const float*)(xsd + (oo.y & 0xffffu)) * *(const float*)(xsd + (oo.y >> 16));
                float vz = *(const float*)(xsd + (oo.z & 0xffffu)) * *(const float*)(xsd + (oo.z >> 16));
                float vw = *(const float*)(xsd + (oo.w & 0xffffu)) * *(const float*)(xsd + (oo.w >> 16));
                uint4 big;
                big.x = tf32_of(vx);
                big.y = tf32_of(vy);
                big.z = tf32_of(vz);
                big.w = tf32_of(vw);
                *(uint4*)(IPBu + d * PP + pg * 4) = big;
            }
        }
        __syncthreads();

        // accumulators init with bias
        float acc[2][2][4];
#pragma unroll
        for (int mt = 0; mt < 2; ++mt)
#pragma unroll
            for (int nt = 0; nt < 2; ++nt) {
                const int c0 = ngrp * 16 + nt * 8 + kd * 2;
                acc[mt][nt][0] = ab_s[c0];
                acc[mt][nt][1] = ab_s[c0 + 1];
                acc[mt][nt][2] = ab_s[c0];
                acc[mt][nt][3] = ab_s[c0 + 1];
            }

        // K loop: 8 kt x 2 mt x 2 nt x 1 mma
#pragma unroll
        for (int kt = 0; kt < 8; ++kt) {
#pragma unroll
            for (int mt = 0; mt < 2; ++mt) {
                const int pr = mgrp * 32 + mt * 16 + qr;
                const uint32_t* rb0 = IPBu + (kt * 8 + kd) * PP + pr;
                const uint32_t* rb1 = IPBu + (kt * 8 + kd + 4) * PP + pr;
                uint32_t a0 = rb0[0], a1 = rb0[8], a2 = rb1[0], a3 = rb1[8];
#pragma unroll
                for (int nt = 0; nt < 2; ++nt) {
                    mma8(acc[mt][nt][0], acc[mt][nt][1], acc[mt][nt][2], acc[mt][nt][3],
                         a0, a1, a2, a3, Bb[kt][nt][0], Bb[kt][nt][1]);
                }
            }
        }

        // epilogue: relu + proj, reduce warp's 16 cols, quad-reduce, write unique slots
#pragma unroll
        for (int mt = 0; mt < 2; ++mt) {
            float lp0 = 0.f, lp1 = 0.f;
#pragma unroll
            for (int nt = 0; nt < 2; ++nt) {
                const int c0 = ngrp * 16 + nt * 8 + kd * 2;
                lp0 += fmaxf(acc[mt][nt][0], 0.f) * pw_s[c0] + fmaxf(acc[mt][nt][1], 0.f) * pw_s[c0 + 1];
                lp1 += fmaxf(acc[mt][nt][2], 0.f) * pw_s[c0] + fmaxf(acc[mt][nt][3], 0.f) * pw_s[c0 + 1];
            }
            lp0 += __shfl_xor_sync(0xffffffffu, lp0, 1);
            lp0 += __shfl_xor_sync(0xffffffffu, lp0, 2);
            lp1 += __shfl_xor_sync(0xffffffffu, lp1, 1);
            lp1 += __shfl_xor_sync(0xffffffffu, lp1, 2);
            if (kd == 0) {
                const int p0 = cbase + mgrp * 32 + mt * 16 + qr;
                part[p0 * 2 + ngrp]       = lp0;
                part[(p0 + 8) * 2 + ngrp] = lp1;
            }
        }
        __syncthreads();   // protects IPB reuse by next chunk's build
    }

    // ---- Phase 3: softmax over 780 (logit assembled from part pairs) ----
    float lm = -3.4e38f;
    for (int p = tid; p < NP; p += THREADS) {
        float lg = part[p * 2] + part[p * 2 + 1] + pb;
        logits_s[p] = lg;
        lm = fmaxf(lm, lg);
    }
#pragma unroll
    for (int o = 16; o > 0; o >>= 1) lm = fmaxf(lm, __shfl_xor_sync(0xffffffffu, lm, o));
    if (lane == 0) rmax[wid] = lm;
    __syncthreads();

    float gmax = rmax[0];
#pragma unroll
    for (int wq = 1; wq < 8; ++wq) gmax = fmaxf(gmax, rmax[wq]);

    float ls = 0.f;
    for (int p = tid; p < NP; p += THREADS) {
        float e = __expf(logits_s[p] - gmax);
        logits_s[p] = e;
        ls += e;
    }
#pragma unroll
    for (int o = 16; o > 0; o >>= 1) ls += __shfl_xor_sync(0xffffffffu, ls, o);
    if (lane == 0) rsum[wid] = ls;
    __syncthreads();

    // ---- Phase 4: weighted sum over pairs (recompute ip), fc dot ----
    float* part4 = (float*)(smem + IPB_OFF);   // IP tile dead; 8 warps x 64 dims
    float accL = 0.f, accH = 0.f;
    for (int p = wid; p < NP; p += 8) {
        const float s = logits_s[p];
        const uint32_t o = offs[p];
        const char* xi = xsc + (o & 0xffffu);
        const char* xj = xsc + (o >> 16);
        accL += s * (*(const float*)(xi + lane * 4)       * *(const float*)(xj + lane * 4));
        accH += s * (*(const float*)(xi + 128 + lane * 4) * *(const float*)(xj + 128 + lane * 4));
    }
    part4[wid * 64 + lane]      = accL;
    part4[wid * 64 + 32 + lane] = accH;
    __syncthreads();

    if (tid < 64) {
        float v = 0.f;
#pragma unroll
        for (int wq = 0; wq < 8; ++wq) v += part4[wq * 64 + tid];
        red_s[tid] = v * fw_s[tid];
    }
    __syncthreads();

    if (tid == 0) {
        float S = 0.f;
#pragma unroll
        for (int wq = 0; wq < 8; ++wq) S += rsum[wq];
        float tt = 0.f;
#pragma unroll
        for (int k = 0; k < 64; ++k) tt += red_s[k];
        out[b] = tt / S + fc_b[0];
    }
}

extern "C" void kernel_launch(void* const* d_in, const int* in_sizes, int n_in,
                              void* d_out, int out_size)
{
    const float* x      = (const float*)d_in[0];
    const float* attn_w = (const float*)d_in[1];
    const float* attn_b = (const float*)d_in[2];
    const float* proj_w = (const float*)d_in[3];
    const float* proj_b = (const float*)d_in[4];
    const float* fc_w   = (const float*)d_in[5];
    const float* fc_b   = (const float*)d_in[6];
    float* out = (float*)d_out;

    cudaFuncSetAttribute(afm_kernel, cudaFuncAttributeMaxDynamicSharedMemorySize, SMEM_TOTAL);
    afm_kernel<<<2048, THREADS, SMEM_TOTAL>>>(x, attn_w, attn_b, proj_w, proj_b, fc_w, fc_b, out);
}

// round 10
// speedup vs baseline: 2.1194x; 1.2670x over previous
#include <cuda_runtime.h>
#include <cstdint>

#define NF 40
#define NP 780        // 40*39/2
#define ED 64
#define AS 32
#define THREADS 256
#define CP 128        // pairs per chunk
#define NCH 7
#define NPAD (NCH*CP) // 896

#define XP 72         // xs pitch in floats: 8B-aligned float2s, 2 words/bank -> CF
#define WP 40         // W tile pitch (40 % 32 == 8)

// ---- dynamic smem byte offsets ----
#define XS_OFF    0        // xs [40][72] f32       11520
#define WB_OFF    11520    // W tf32 [64][40]       10240
#define OFFS_OFF  21760    // [896] u32              3584
#define PART_OFF  25344    // [896][2] f32           7168
#define LOG_OFF   32512    // [896] f32              3584
#define P4_OFF    36096    // [8][64] f32            2048
#define AB_OFF    38144    // 32 f32
#define PW_OFF    38272    // 32 f32
#define FW_OFF    38400    // 64 f32
#define RMAX_OFF  38656    // 8 f32
#define RSUM_OFF  38688    // 8 f32
#define RED_OFF   38720    // 64 f32
#define SMEM_TOTAL 38976   // x3 CTAs by smem is easy; regs are the occ limiter

__device__ __forceinline__ uint32_t tf32_of(float v) {
    uint32_t r; asm("cvt.rna.tf32.f32 %0, %1;" : "=r"(r) : "f"(v)); return r;
}

__device__ __forceinline__ void mma8(float& c0, float& c1, float& c2, float& c3,
                                     uint32_t a0, uint32_t a1, uint32_t a2, uint32_t a3,
                                     uint32_t b0, uint32_t b1) {
    asm("mma.sync.aligned.m16n8k8.row.col.f32.tf32.tf32.f32 "
        "{%0,%1,%2,%3}, {%4,%5,%6,%7}, {%8,%9}, {%0,%1,%2,%3};"
        : "+f"(c0), "+f"(c1), "+f"(c2), "+f"(c3)
        : "r"(a0), "r"(a1), "r"(a2), "r"(a3), "r"(b0), "r"(b1));
}

__global__ __launch_bounds__(THREADS, 3) void afm_kernel(
    const float* __restrict__ x,
    const float* __restrict__ attn_w,
    const float* __restrict__ attn_b,
    const float* __restrict__ proj_w,
    const float* __restrict__ proj_b,
    const float* __restrict__ fc_w,
    const float* __restrict__ fc_b,
    float* __restrict__ out)
{
    extern __shared__ char smem[];
    float* xs        = (float*)(smem + XS_OFF);
    float* logits_s  = (float*)(smem + LOG_OFF);
    float* part      = (float*)(smem + PART_OFF);   // [896][2]
    float* p4        = (float*)(smem + P4_OFF);     // [8][64]
    float* ab_s      = (float*)(smem + AB_OFF);
    float* pw_s      = (float*)(smem + PW_OFF);
    float* fw_s      = (float*)(smem + FW_OFF);
    float* rmax      = (float*)(smem + RMAX_OFF);
    float* rsum      = (float*)(smem + RSUM_OFF);
    float* red_s     = (float*)(smem + RED_OFF);
    uint32_t* offs   = (uint32_t*)(smem + OFFS_OFF);
    uint32_t* WBu    = (uint32_t*)(smem + WB_OFF);

    const int tid  = threadIdx.x;
    const int lane = tid & 31;
    const int wid  = tid >> 5;
    const int b    = blockIdx.x;

    // ---- Phase 1: stage inputs ----
    const float* xb = x + (long long)b * (NF * ED);
    for (int idx = tid; idx < NF * ED; idx += THREADS)
        xs[(idx >> 6) * XP + (idx & 63)] = xb[idx];

    // W tf32 tile [d][40]
    for (int e = tid; e < ED * AS; e += THREADS) {
        int d = e >> 5, n = e & 31;
        WBu[d * WP + n] = tf32_of(attn_w[e]);
    }

    if (tid < AS) { pw_s[tid] = proj_w[tid]; ab_s[tid] = attn_b[tid]; }
    if (tid < ED) fw_s[tid] = fc_w[tid];

    // packed xs byte-offsets per pair (dead pairs -> (0,0): garbage part, never read)
    for (int p = tid; p < NPAD; p += THREADS) {
        uint32_t o = 0;
        if (p < NP) {
            int i = 0, rem = p;
            while (rem >= NF - 1 - i) { rem -= NF - 1 - i; ++i; }
            int j = i + 1 + rem;
            o = (uint32_t)(i * (XP * 4)) | ((uint32_t)(j * (XP * 4)) << 16);
        }
        offs[p] = o;
    }
    const float pb = proj_b[0];
    __syncthreads();

    const int kd   = lane & 3;        // threadID_in_group (k-slot)
    const int qr   = lane >> 2;       // groupID (row)
    const int mgrp = wid & 3;         // 4 M-groups x 32 pairs
    const int ngrp = wid >> 2;        // 2 N-groups x 16 cols

    // ---- hoist B fragments with K-permutation: slot(kt,kd) -> d = 8kt+2kd, slot kd+4 -> +1 ----
    uint32_t Bb[8][2][2];
#pragma unroll
    for (int kt = 0; kt < 8; ++kt) {
#pragma unroll
        for (int nt = 0; nt < 2; ++nt) {
            const int nc = ngrp * 16 + nt * 8 + qr;
            Bb[kt][nt][0] = WBu[(kt * 8 + kd * 2) * WP + nc];
            Bb[kt][nt][1] = WBu[(kt * 8 + kd * 2 + 1) * WP + nc];
        }
    }

    // hoist bias and proj weights for this thread's columns
    float bia[2][2], pww[2][2];
#pragma unroll
    for (int nt = 0; nt < 2; ++nt) {
        const int c0 = ngrp * 16 + nt * 8 + kd * 2;
        bia[nt][0] = ab_s[c0];     bia[nt][1] = ab_s[c0 + 1];
        pww[nt][0] = pw_s[c0];     pww[nt][1] = pw_s[c0 + 1];
    }

    const char* xsc = (const char*)xs;

    // ---- Phase 2: barrier-free chunked tf32 MMA, A-frags built in registers ----
    for (int t = 0; t < NCH; ++t) {
        const int pb0 = t * CP + mgrp * 32 + qr;
        const uint32_t oA = offs[pb0];        // mt0, rows qr
        const uint32_t oB = offs[pb0 + 8];    // mt0, rows qr+8
        const uint32_t oC = offs[pb0 + 16];   // mt1, rows qr
        const uint32_t oD = offs[pb0 + 24];   // mt1, rows qr+8
        const char* xiA = xsc + (oA & 0xffffu); const char* xjA = xsc + (oA >> 16);
        const char* xiB = xsc + (oB & 0xffffu); const char* xjB = xsc + (oB >> 16);
        const char* xiC = xsc + (oC & 0xffffu); const char* xjC = xsc + (oC >> 16);
        const char* xiD = xsc + (oD & 0xffffu); const char* xjD = xsc + (oD >> 16);

        float acc[2][2][4];
#pragma unroll
        for (int mt = 0; mt < 2; ++mt)
#pragma unroll
            for (int nt = 0; nt < 2; ++nt) {
                acc[mt][nt][0] = bia[nt][0];
                acc[mt][nt][1] = bia[nt][1];
                acc[mt][nt][2] = bia[nt][0];
                acc[mt][nt][3] = bia[nt][1];
            }

#pragma unroll
        for (int kt = 0; kt < 8; ++kt) {
            const int db = kt * 32 + kd * 8;   // byte offset of d = 8kt + 2kd
            const float2 iA = *(const float2*)(xiA + db);
            const float2 jA = *(const float2*)(xjA + db);
            const float2 iB = *(const float2*)(xiB + db);
            const float2 jB = *(const float2*)(xjB + db);
            uint32_t a0 = tf32_of(iA.x * jA.x);
            uint32_t a2 = tf32_of(iA.y * jA.y);
            uint32_t a1 = tf32_of(iB.x * jB.x);
            uint32_t a3 = tf32_of(iB.y * jB.y);
            mma8(acc[0][0][0], acc[0][0][1], acc[0][0][2], acc[0][0][3],
                 a0, a1, a2, a3, Bb[kt][0][0], Bb[kt][0][1]);
            mma8(acc[0][1][0], acc[0][1][1], acc[0][1][2], acc[0][1][3],
                 a0, a1, a2, a3, Bb[kt][1][0], Bb[kt][1][1]);

            const float2 iC = *(const float2*)(xiC + db);
            const float2 jC = *(const float2*)(xjC + db);
            const float2 iD = *(const float2*)(xiD + db);
            const float2 jD = *(const float2*)(xjD + db);
            uint32_t c0 = tf32_of(iC.x * jC.x);
            uint32_t c2 = tf32_of(iC.y * jC.y);
            uint32_t c1 = tf32_of(iD.x * jD.x);
            uint32_t c3 = tf32_of(iD.y * jD.y);
            mma8(acc[1][0][0], acc[1][0][1], acc[1][0][2], acc[1][0][3],
                 c0, c1, c2, c3, Bb[kt][0][0], Bb[kt][0][1]);
            mma8(acc[1][1][0], acc[1][1][1], acc[1][1][2], acc[1][1][3],
                 c0, c1, c2, c3, Bb[kt][1][0], Bb[kt][1][1]);
        }

        // epilogue: relu + proj, quad-reduce, write unique part slots (no barrier)
#pragma unroll
        for (int mt = 0; mt < 2; ++mt) {
            float lp0 = 0.f, lp1 = 0.f;
#pragma unroll
            for (int nt = 0; nt < 2; ++nt) {
                lp0 += fmaxf(acc[mt][nt][0], 0.f) * pww[nt][0] + fmaxf(acc[mt][nt][1], 0.f) * pww[nt][1];
                lp1 += fmaxf(acc[mt][nt][2], 0.f) * pww[nt][0] + fmaxf(acc[mt][nt][3], 0.f) * pww[nt][1];
            }
            lp0 += __shfl_xor_sync(0xffffffffu, lp0, 1);
            lp0 += __shfl_xor_sync(0xffffffffu, lp0, 2);
            lp1 += __shfl_xor_sync(0xffffffffu, lp1, 1);
            lp1 += __shfl_xor_sync(0xffffffffu, lp1, 2);
            if (kd == 0) {
                const int p0 = pb0 + mt * 16;
                part[p0 * 2 + ngrp]       = lp0;
                part[(p0 + 8) * 2 + ngrp] = lp1;
            }
        }
    }
    __syncthreads();

    // ---- Phase 3: softmax over 780 (logit assembled from part pairs) ----
    float lm = -3.4e38f;
    for (int p = tid; p < NP; p += THREADS) {
        float lg = part[p * 2] + part[p * 2 + 1] + pb;
        logits_s[p] = lg;
        lm = fmaxf(lm, lg);
    }
#pragma unroll
    for (int o = 16; o > 0; o >>= 1) lm = fmaxf(lm, __shfl_xor_sync(0xffffffffu, lm, o));
    if (lane == 0) rmax[wid] = lm;
    __syncthreads();

    float gmax = rmax[0];
#pragma unroll
    for (int wq = 1; wq < 8; ++wq) gmax = fmaxf(gmax, rmax[wq]);

    float ls = 0.f;
    for (int p = tid; p < NP; p += THREADS) {
        float e = __expf(logits_s[p] - gmax);
        logits_s[p] = e;
        ls += e;
    }
#pragma unroll
    for (int o = 16; o > 0; o >>= 1) ls += __shfl_xor_sync(0xffffffffu, ls, o);
    if (lane == 0) rsum[wid] = ls;
    __syncthreads();

    // ---- Phase 4: weighted sum grouped by field i (x_i hoisted per row) ----
    float axx = 0.f, axy = 0.f;
    for (int i = wid; i < NF - 1; i += 8) {
        const int rowstart = i * (79 - i) / 2;        // pairs (i, j>i) start here
        const float2 xi = *(const float2*)(xs + i * XP + 2 * lane);
        const float* lrow = logits_s + rowstart - i - 1;
        for (int j = i + 1; j < NF; ++j) {
            const float s = lrow[j];                  // logits_s[rowstart + j-i-1]
            const float2 xj = *(const float2*)(xs + j * XP + 2 * lane);
            axx += s * xi.x * xj.x;
            axy += s * xi.y * xj.y;
        }
    }
    *(float2*)(p4 + wid * 64 + 2 * lane) = make_float2(axx, axy);
    __syncthreads();

    if (tid < 64) {
        float v = 0.f;
#pragma unroll
        for (int wq = 0; wq < 8; ++wq) v += p4[wq * 64 + tid];
        red_s[tid] = v * fw_s[tid];
    }
    __syncthreads();

    if (tid == 0) {
        float S = 0.f;
#pragma unroll
        for (int wq = 0; wq < 8; ++wq) S += rsum[wq];
        float tt = 0.f;
#pragma unroll
        for (int k = 0; k < 64; ++k) tt += red_s[k];
        out[b] = tt / S + fc_b[0];
    }
}

extern "C" void kernel_launch(void* const* d_in, const int* in_sizes, int n_in,
                              void* d_out, int out_size)
{
    const float* x      = (const float*)d_in[0];
    const float* attn_w = (const float*)d_in[1];
    const float* attn_b = (const float*)d_in[2];
    const float* proj_w = (const float*)d_in[3];
    const float* proj_b = (const float*)d_in[4];
    const float* fc_w   = (const float*)d_in[5];
    const float* fc_b   = (const float*)d_in[6];
    float* out = (float*)d_out;

    cudaFuncSetAttribute(afm_kernel, cudaFuncAttributeMaxDynamicSharedMemorySize, SMEM_TOTAL);
    afm_kernel<<<2048, THREADS, SMEM_TOTAL>>>(x, attn_w, attn_b, proj_w, proj_b, fc_w, fc_b, out);
}

// round 11
// speedup vs baseline: 2.1930x; 1.0348x over previous
#include <cuda_runtime.h>
#include <cstdint>

#define NF 40
#define NP 780        // 40*39/2
#define ED 64
#define AS 32
#define THREADS 256
#define CP 128        // pairs per chunk
#define NCH 7
#define NPAD (NCH*CP) // 896

#define XP 72         // xs pitch in floats: 8B-aligned float2s, 2 words/bank -> CF
#define WP 40         // W tile pitch (40 % 32 == 8)

// ---- dynamic smem byte offsets ----
#define XS_OFF    0        // xs [40][72] f32       11520
#define WB_OFF    11520    // W tf32 [64][40]       10240
#define OFFS_OFF  21760    // [896] u32              3584
#define PART_OFF  25344    // [896][2] f32           7168
#define LOG_OFF   32512    // [896] f32              3584
#define P4_OFF    36096    // [8][64] f32            2048
#define AB_OFF    38144    // 32 f32
#define PW_OFF    38272    // 32 f32
#define FW_OFF    38400    // 64 f32
#define RMAX_OFF  38656    // 8 f32
#define RSUM_OFF  38688    // 8 f32
#define RED_OFF   38720    // 64 f32
#define SMEM_TOTAL 38976

__device__ __forceinline__ uint32_t tf32_of(float v) {
    uint32_t r; asm("cvt.rna.tf32.f32 %0, %1;" : "=r"(r) : "f"(v)); return r;
}

// packed f32x2 multiply; halves then feed mma directly (HW truncates to tf32)
#define MUL2(out, a, b) asm("mul.rn.f32x2 %0, %1, %2;" : "=l"(out) : "l"(a), "l"(b))
#define UNPK(lo, hi, v) asm("mov.b64 {%0, %1}, %2;" : "=r"(lo), "=r"(hi) : "l"(v))

__device__ __forceinline__ void mma8(float& c0, float& c1, float& c2, float& c3,
                                     uint32_t a0, uint32_t a1, uint32_t a2, uint32_t a3,
                                     uint32_t b0, uint32_t b1) {
    asm("mma.sync.aligned.m16n8k8.row.col.f32.tf32.tf32.f32 "
        "{%0,%1,%2,%3}, {%4,%5,%6,%7}, {%8,%9}, {%0,%1,%2,%3};"
        : "+f"(c0), "+f"(c1), "+f"(c2), "+f"(c3)
        : "r"(a0), "r"(a1), "r"(a2), "r"(a3), "r"(b0), "r"(b1));
}

__global__ __launch_bounds__(THREADS, 3) void afm_kernel(
    const float* __restrict__ x,
    const float* __restrict__ attn_w,
    const float* __restrict__ attn_b,
    const float* __restrict__ proj_w,
    const float* __restrict__ proj_b,
    const float* __restrict__ fc_w,
    const float* __restrict__ fc_b,
    float* __restrict__ out)
{
    extern __shared__ char smem[];
    float* xs        = (float*)(smem + XS_OFF);
    float* logits_s  = (float*)(smem + LOG_OFF);
    float* part      = (float*)(smem + PART_OFF);   // [896][2]
    float* p4        = (float*)(smem + P4_OFF);     // [8][64]
    float* ab_s      = (float*)(smem + AB_OFF);
    float* pw_s      = (float*)(smem + PW_OFF);
    float* fw_s      = (float*)(smem + FW_OFF);
    float* rmax      = (float*)(smem + RMAX_OFF);
    float* rsum      = (float*)(smem + RSUM_OFF);
    float* red_s     = (float*)(smem + RED_OFF);
    uint32_t* offs   = (uint32_t*)(smem + OFFS_OFF);
    uint32_t* WBu    = (uint32_t*)(smem + WB_OFF);

    const int tid  = threadIdx.x;
    const int lane = tid & 31;
    const int wid  = tid >> 5;
    const int b    = blockIdx.x;

    // ---- Phase 1: stage inputs ----
    const float* xb = x + (long long)b * (NF * ED);
    for (int idx = tid; idx < NF * ED; idx += THREADS)
        xs[(idx >> 6) * XP + (idx & 63)] = xb[idx];

    // W tf32 tile [d][40] (rna-rounded; W-side rounding kept, it's one-time)
    for (int e = tid; e < ED * AS; e += THREADS) {
        int d = e >> 5, n = e & 31;
        WBu[d * WP + n] = tf32_of(attn_w[e]);
    }

    if (tid < AS) { pw_s[tid] = proj_w[tid]; ab_s[tid] = attn_b[tid]; }
    if (tid < ED) fw_s[tid] = fc_w[tid];

    // packed xs byte-offsets per pair (dead pairs -> (0,0): garbage part, never read)
    for (int p = tid; p < NPAD; p += THREADS) {
        uint32_t o = 0;
        if (p < NP) {
            int i = 0, rem = p;
            while (rem >= NF - 1 - i) { rem -= NF - 1 - i; ++i; }
            int j = i + 1 + rem;
            o = (uint32_t)(i * (XP * 4)) | ((uint32_t)(j * (XP * 4)) << 16);
        }
        offs[p] = o;
    }
    const float pb = proj_b[0];
    __syncthreads();

    const int kd   = lane & 3;        // threadID_in_group (k-slot)
    const int qr   = lane >> 2;       // groupID (row)
    const int mgrp = wid & 3;         // 4 M-groups x 32 pairs
    const int ngrp = wid >> 2;        // 2 N-groups x 16 cols

    // ---- hoist B fragments with K-permutation: slot(kt,kd) -> d = 8kt+2kd, slot kd+4 -> +1 ----
    uint32_t Bb[8][2][2];
#pragma unroll
    for (int kt = 0; kt < 8; ++kt) {
#pragma unroll
        for (int nt = 0; nt < 2; ++nt) {
            const int nc = ngrp * 16 + nt * 8 + qr;
            Bb[kt][nt][0] = WBu[(kt * 8 + kd * 2) * WP + nc];
            Bb[kt][nt][1] = WBu[(kt * 8 + kd * 2 + 1) * WP + nc];
        }
    }

    // hoist bias and proj weights for this thread's columns
    float bia[2][2], pww[2][2];
#pragma unroll
    for (int nt = 0; nt < 2; ++nt) {
        const int c0 = ngrp * 16 + nt * 8 + kd * 2;
        bia[nt][0] = ab_s[c0];     bia[nt][1] = ab_s[c0 + 1];
        pww[nt][0] = pw_s[c0];     pww[nt][1] = pw_s[c0 + 1];
    }

    const char* xsc = (const char*)xs;

    // ---- Phase 2: barrier-free chunked tf32 MMA, A-frags = raw f32 products ----
    for (int t = 0; t < NCH; ++t) {
        const int pb0 = t * CP + mgrp * 32 + qr;
        const uint32_t oA = offs[pb0];
        const uint32_t oB = offs[pb0 + 8];
        const uint32_t oC = offs[pb0 + 16];
        const uint32_t oD = offs[pb0 + 24];
        const char* xiA = xsc + (oA & 0xffffu); const char* xjA = xsc + (oA >> 16);
        const char* xiB = xsc + (oB & 0xffffu); const char* xjB = xsc + (oB >> 16);
        const char* xiC = xsc + (oC & 0xffffu); const char* xjC = xsc + (oC >> 16);
        const char* xiD = xsc + (oD & 0xffffu); const char* xjD = xsc + (oD >> 16);

        float acc[2][2][4];
#pragma unroll
        for (int mt = 0; mt < 2; ++mt)
#pragma unroll
            for (int nt = 0; nt < 2; ++nt) {
                acc[mt][nt][0] = bia[nt][0];
                acc[mt][nt][1] = bia[nt][1];
                acc[mt][nt][2] = bia[nt][0];
                acc[mt][nt][3] = bia[nt][1];
            }

#pragma unroll
        for (int kt = 0; kt < 8; ++kt) {
            const int db = kt * 32 + kd * 8;   // byte offset of d = 8kt + 2kd
            unsigned long long iA = *(const unsigned long long*)(xiA + db);
            unsigned long long jA = *(const unsigned long long*)(xjA + db);
            unsigned long long iB = *(const unsigned long long*)(xiB + db);
            unsigned long long jB = *(const unsigned long long*)(xjB + db);
            unsigned long long pA, pBv;
            MUL2(pA, iA, jA);
            MUL2(pBv, iB, jB);
            uint32_t a0, a2, a1, a3;
            UNPK(a0, a2, pA);
            UNPK(a1, a3, pBv);
            mma8(acc[0][0][0], acc[0][0][1], acc[0][0][2], acc[0][0][3],
                 a0, a1, a2, a3, Bb[kt][0][0], Bb[kt][0][1]);
            mma8(acc[0][1][0], acc[0][1][1], acc[0][1][2], acc[0][1][3],
                 a0, a1, a2, a3, Bb[kt][1][0], Bb[kt][1][1]);

            unsigned long long iC = *(const unsigned long long*)(xiC + db);
            unsigned long long jC = *(const unsigned long long*)(xjC + db);
            unsigned long long iD = *(const unsigned long long*)(xiD + db);
            unsigned long long jD = *(const unsigned long long*)(xjD + db);
            unsigned long long pC, pD;
            MUL2(pC, iC, jC);
            MUL2(pD, iD, jD);
            uint32_t c0, c2, c1, c3;
            UNPK(c0, c2, pC);
            UNPK(c1, c3, pD);
            mma8(acc[1][0][0], acc[1][0][1], acc[1][0][2], acc[1][0][3],
                 c0, c1, c2, c3, Bb[kt][0][0], Bb[kt][0][1]);
            mma8(acc[1][1][0], acc[1][1][1], acc[1][1][2], acc[1][1][3],
                 c0, c1, c2, c3, Bb[kt][1][0], Bb[kt][1][1]);
        }

        // epilogue: relu + proj, quad-reduce, write unique part slots (no barrier)
#pragma unroll
        for (int mt = 0; mt < 2; ++mt) {
            float lp0 = 0.f, lp1 = 0.f;
#pragma unroll
            for (int nt = 0; nt < 2; ++nt) {
                lp0 += fmaxf(acc[mt][nt][0], 0.f) * pww[nt][0] + fmaxf(acc[mt][nt][1], 0.f) * pww[nt][1];
                lp1 += fmaxf(acc[mt][nt][2], 0.f) * pww[nt][0] + fmaxf(acc[mt][nt][3], 0.f) * pww[nt][1];
            }
            lp0 += __shfl_xor_sync(0xffffffffu, lp0, 1);
            lp0 += __shfl_xor_sync(0xffffffffu, lp0, 2);
            lp1 += __shfl_xor_sync(0xffffffffu, lp1, 1);
            lp1 += __shfl_xor_sync(0xffffffffu, lp1, 2);
            if (kd == 0) {
                const int p0 = pb0 + mt * 16;
                part[p0 * 2 + ngrp]       = lp0;
                part[(p0 + 8) * 2 + ngrp] = lp1;
            }
        }
    }
    __syncthreads();

    // ---- Phase 3: softmax over 780 (logit assembled from part pairs) ----
    float lm = -3.4e38f;
    for (int p = tid; p < NP; p += THREADS) {
        float lg = part[p * 2] + part[p * 2 + 1] + pb;
        logits_s[p] = lg;
        lm = fmaxf(lm, lg);
    }
#pragma unroll
    for (int o = 16; o > 0; o >>= 1) lm = fmaxf(lm, __shfl_xor_sync(0xffffffffu, lm, o));
    if (lane == 0) rmax[wid] = lm;
    __syncthreads();

    float gmax = rmax[0];
#pragma unroll
    for (int wq = 1; wq < 8; ++wq) gmax = fmaxf(gmax, rmax[wq]);

    float ls = 0.f;
    for (int p = tid; p < NP; p += THREADS) {
        float e = __expf(logits_s[p] - gmax);
        logits_s[p] = e;
        ls += e;
    }
#pragma unroll
    for (int o = 16; o > 0; o >>= 1) ls += __shfl_xor_sync(0xffffffffu, ls, o);
    if (lane == 0) rsum[wid] = ls;
    __syncthreads();

    // ---- Phase 4: weighted sum grouped by field i (x_i hoisted per row) ----
    float axx = 0.f, axy = 0.f;
    for (int i = wid; i < NF - 1; i += 8) {
        const int rowstart = i * (79 - i) / 2;
        const float2 xi = *(const float2*)(xs + i * XP + 2 * lane);
        const float* lrow = logits_s + rowstart - i - 1;
        for (int j = i + 1; j < NF; ++j) {
            const float s = lrow[j];
            const float2 xj = *(const float2*)(xs + j * XP + 2 * lane);
            axx += s * xi.x * xj.x;
            axy += s * xi.y * xj.y;
        }
    }
    *(float2*)(p4 + wid * 64 + 2 * lane) = make_float2(axx, axy);
    __syncthreads();

    if (tid < 64) {
        float v = 0.f;
#pragma unroll
        for (int wq = 0; wq < 8; ++wq) v += p4[wq * 64 + tid];
        red_s[tid] = v * fw_s[tid];
    }
    __syncthreads();

    if (tid == 0) {
        float S = 0.f;
#pragma unroll
        for (int wq = 0; wq < 8; ++wq) S += rsum[wq];
        float tt = 0.f;
#pragma unroll
        for (int k = 0; k < 64; ++k) tt += red_s[k];
        out[b] = tt / S + fc_b[0];
    }
}

extern "C" void kernel_launch(void* const* d_in, const int* in_sizes, int n_in,
                              void* d_out, int out_size)
{
    const float* x      = (const float*)d_in[0];
    const float* attn_w = (const float*)d_in[1];
    const float* attn_b = (const float*)d_in[2];
    const float* proj_w = (const float*)d_in[3];
    const float* proj_b = (const float*)d_in[4];
    const float* fc_w   = (const float*)d_in[5];
    const float* fc_b   = (const float*)d_in[6];
    float* out = (float*)d_out;

    cudaFuncSetAttribute(afm_kernel, cudaFuncAttributeMaxDynamicSharedMemorySize, SMEM_TOTAL);
    afm_kernel<<<2048, THREADS, SMEM_TOTAL>>>(x, attn_w, attn_b, proj_w, proj_b, fc_w, fc_b, out);
}

// round 12
// speedup vs baseline: 2.4310x; 1.1085x over previous
#include <cuda_runtime.h>
#include <cstdint>

#define NF 40
#define NP 780        // 40*39/2
#define ED 64
#define AS 32
#define THREADS 256
#define CP 128
#define NCH 7
#define NPAD (NCH*CP) // 896

#define XP 72         // xs pitch (f32): float2-aligned, conflict-free
#define WP 40         // W tile pitch (40 % 32 == 8)
#define SP 40         // S pitch (40 % 32 == 8 -> CF paired loads)
#define YP 66         // Y pitch (row*264B keeps float2 align)

// ---- dynamic smem byte offsets ----
#define XS_OFF    0        // xs [40][72] f32      11520
#define WB_OFF    11520    // W tf32 [64][40]      10240
#define OFFS_OFF  21760    // [896] u32             3584
#define PART_OFF  25344    // [896][2] f32          7168
#define LOG_OFF   32512    // [896] f32             3584
#define S_OFF     36096    // S [48][40] f32        7680
#define Y_OFF     43776    // Y [40][66] f32       10560
#define P4_OFF    54336    // [4][64] f32           1024
#define AB_OFF    55360    // 32 f32
#define PW_OFF    55488    // 32 f32
#define FW_OFF    55616    // 64 f32
#define RMAX_OFF  55872    // 8 f32
#define RSUM_OFF  55904    // 8 f32
#define RED_OFF   55936    // 64 f32
#define SMEM_TOTAL 56192   // x3 CTAs fits easily

__device__ __forceinline__ uint32_t tf32_of(float v) {
    uint32_t r; asm("cvt.rna.tf32.f32 %0, %1;" : "=r"(r) : "f"(v)); return r;
}

__device__ __forceinline__ void mma8(float& c0, float& c1, float& c2, float& c3,
                                     uint32_t a0, uint32_t a1, uint32_t a2, uint32_t a3,
                                     uint32_t b0, uint32_t b1) {
    asm("mma.sync.aligned.m16n8k8.row.col.f32.tf32.tf32.f32 "
        "{%0,%1,%2,%3}, {%4,%5,%6,%7}, {%8,%9}, {%0,%1,%2,%3};"
        : "+f"(c0), "+f"(c1), "+f"(c2), "+f"(c3)
        : "r"(a0), "r"(a1), "r"(a2), "r"(a3), "r"(b0), "r"(b1));
}

// closed-form triangular index inverse: returns i, sets rs = rowstart(i).
// exact at boundaries: 6241 - 8*rowstart(i) = (79-2i)^2.
__device__ __forceinline__ int row_of(int p, int& rs) {
    int i = (int)((79.0f - sqrtf((float)(6241 - 8 * p))) * 0.5f);
    rs = i * (79 - i) / 2;
    if (p < rs) { --i; rs = i * (79 - i) / 2; }
    else if (p - rs >= 39 - i) { rs += 39 - i; ++i; }
    return i;
}

__global__ __launch_bounds__(THREADS, 3) void afm_kernel(
    const float* __restrict__ x,
    const float* __restrict__ attn_w,
    const float* __restrict__ attn_b,
    const float* __restrict__ proj_w,
    const float* __restrict__ proj_b,
    const float* __restrict__ fc_w,
    const float* __restrict__ fc_b,
    float* __restrict__ out)
{
    extern __shared__ char smem[];
    float* xs        = (float*)(smem + XS_OFF);
    float* logits_s  = (float*)(smem + LOG_OFF);
    float* part      = (float*)(smem + PART_OFF);
    float* Sm        = (float*)(smem + S_OFF);
    float* Ym        = (float*)(smem + Y_OFF);
    float* p4        = (float*)(smem + P4_OFF);
    float* ab_s      = (float*)(smem + AB_OFF);
    float* pw_s      = (float*)(smem + PW_OFF);
    float* fw_s      = (float*)(smem + FW_OFF);
    float* rmax      = (float*)(smem + RMAX_OFF);
    float* rsum      = (float*)(smem + RSUM_OFF);
    float* red_s     = (float*)(smem + RED_OFF);
    uint32_t* offs   = (uint32_t*)(smem + OFFS_OFF);
    uint32_t* WBu    = (uint32_t*)(smem + WB_OFF);

    const int tid  = threadIdx.x;
    const int lane = tid & 31;
    const int wid  = tid >> 5;
    const int b    = blockIdx.x;

    // ---- Phase 1: stage inputs ----
    const float* xb = x + (long long)b * (NF * ED);
    for (int idx = tid; idx < NF * ED; idx += THREADS)
        xs[(idx >> 6) * XP + (idx & 63)] = xb[idx];

    for (int e = tid; e < ED * AS; e += THREADS) {
        int d = e >> 5, n = e & 31;
        WBu[d * WP + n] = tf32_of(attn_w[e]);
    }

    if (tid < AS) { pw_s[tid] = proj_w[tid]; ab_s[tid] = attn_b[tid]; }
    if (tid < ED) fw_s[tid] = fc_w[tid];

    // packed xs byte-offsets per pair via closed form (dead pairs -> 0)
    for (int p = tid; p < NPAD; p += THREADS) {
        uint32_t o = 0;
        if (p < NP) {
            int rs;
            int i = row_of(p, rs);
            int j = i + 1 + (p - rs);
            o = (uint32_t)(i * (XP * 4)) | ((uint32_t)(j * (XP * 4)) << 16);
        }
        offs[p] = o;
    }
    const float pb = proj_b[0];
    __syncthreads();

    const int kd   = lane & 3;
    const int qr   = lane >> 2;
    const int mgrp = wid & 3;
    const int ngrp = wid >> 2;

    // ---- hoist B fragments (K-permuted: slots kd,kd+4 -> d = 8kt+2kd, +1) ----
    uint32_t Bb[8][2][2];
#pragma unroll
    for (int kt = 0; kt < 8; ++kt) {
#pragma unroll
        for (int nt = 0; nt < 2; ++nt) {
            const int nc = ngrp * 16 + nt * 8 + qr;
            Bb[kt][nt][0] = WBu[(kt * 8 + kd * 2) * WP + nc];
            Bb[kt][nt][1] = WBu[(kt * 8 + kd * 2 + 1) * WP + nc];
        }
    }

    float bia[2][2], pww[2][2];
#pragma unroll
    for (int nt = 0; nt < 2; ++nt) {
        const int c0 = ngrp * 16 + nt * 8 + kd * 2;
        bia[nt][0] = ab_s[c0];     bia[nt][1] = ab_s[c0 + 1];
        pww[nt][0] = pw_s[c0];     pww[nt][1] = pw_s[c0 + 1];
    }

    const char* xsc = (const char*)xs;

    // ---- Phase 2: barrier-free chunked tf32 MMA (raw-f32 products) ----
    for (int t = 0; t < NCH; ++t) {
        const int pb0 = t * CP + mgrp * 32 + qr;
        const uint32_t oA = offs[pb0];
        const uint32_t oB = offs[pb0 + 8];
        const uint32_t oC = offs[pb0 + 16];
        const uint32_t oD = offs[pb0 + 24];
        const char* xiA = xsc + (oA & 0xffffu); const char* xjA = xsc + (oA >> 16);
        const char* xiB = xsc + (oB & 0xffffu); const char* xjB = xsc + (oB >> 16);
        const char* xiC = xsc + (oC & 0xffffu); const char* xjC = xsc + (oC >> 16);
        const char* xiD = xsc + (oD & 0xffffu); const char* xjD = xsc + (oD >> 16);

        float acc[2][2][4];
#pragma unroll
        for (int mt = 0; mt < 2; ++mt)
#pragma unroll
            for (int nt = 0; nt < 2; ++nt) {
                acc[mt][nt][0] = bia[nt][0];
                acc[mt][nt][1] = bia[nt][1];
                acc[mt][nt][2] = bia[nt][0];
                acc[mt][nt][3] = bia[nt][1];
            }

#pragma unroll
        for (int kt = 0; kt < 8; ++kt) {
            const int db = kt * 32 + kd * 8;
            const float2 iA = *(const float2*)(xiA + db);
            const float2 jA = *(const float2*)(xjA + db);
            const float2 iB = *(const float2*)(xiB + db);
            const float2 jB = *(const float2*)(xjB + db);
            uint32_t a0 = __float_as_uint(iA.x * jA.x);
            uint32_t a2 = __float_as_uint(iA.y * jA.y);
            uint32_t a1 = __float_as_uint(iB.x * jB.x);
            uint32_t a3 = __float_as_uint(iB.y * jB.y);
            mma8(acc[0][0][0], acc[0][0][1], acc[0][0][2], acc[0][0][3],
                 a0, a1, a2, a3, Bb[kt][0][0], Bb[kt][0][1]);
            mma8(acc[0][1][0], acc[0][1][1], acc[0][1][2], acc[0][1][3],
                 a0, a1, a2, a3, Bb[kt][1][0], Bb[kt][1][1]);

            const float2 iC = *(const float2*)(xiC + db);
            const float2 jC = *(const float2*)(xjC + db);
            const float2 iD = *(const float2*)(xiD + db);
            const float2 jD = *(const float2*)(xjD + db);
            uint32_t c0 = __float_as_uint(iC.x * jC.x);
            uint32_t c2 = __float_as_uint(iC.y * jC.y);
            uint32_t c1 = __float_as_uint(iD.x * jD.x);
            uint32_t c3 = __float_as_uint(iD.y * jD.y);
            mma8(acc[1][0][0], acc[1][0][1], acc[1][0][2], acc[1][0][3],
                 c0, c1, c2, c3, Bb[kt][0][0], Bb[kt][0][1]);
            mma8(acc[1][1][0], acc[1][1][1], acc[1][1][2], acc[1][1][3],
                 c0, c1, c2, c3, Bb[kt][1][0], Bb[kt][1][1]);
        }

#pragma unroll
        for (int mt = 0; mt < 2; ++mt) {
            float lp0 = 0.f, lp1 = 0.f;
#pragma unroll
            for (int nt = 0; nt < 2; ++nt) {
                lp0 += fmaxf(acc[mt][nt][0], 0.f) * pww[nt][0] + fmaxf(acc[mt][nt][1], 0.f) * pww[nt][1];
                lp1 += fmaxf(acc[mt][nt][2], 0.f) * pww[nt][0] + fmaxf(acc[mt][nt][3], 0.f) * pww[nt][1];
            }
            lp0 += __shfl_xor_sync(0xffffffffu, lp0, 1);
            lp0 += __shfl_xor_sync(0xffffffffu, lp0, 2);
            lp1 += __shfl_xor_sync(0xffffffffu, lp1, 1);
            lp1 += __shfl_xor_sync(0xffffffffu, lp1, 2);
            if (kd == 0) {
                const int p0 = pb0 + mt * 16;
                part[p0 * 2 + ngrp]       = lp0;
                part[(p0 + 8) * 2 + ngrp] = lp1;
            }
        }
    }

    // zero S (48x40) before the sync that precedes the scatter
    {
        uint4 z = make_uint4(0, 0, 0, 0);
        uint4* S4 = (uint4*)Sm;
        for (int idx = tid; idx < 48 * SP / 4; idx += THREADS) S4[idx] = z;
    }
    __syncthreads();

    // ---- Phase 3: softmax (max, then exp + scatter into symmetric S) ----
    float lm = -3.4e38f;
    for (int p = tid; p < NP; p += THREADS) {
        float lg = part[p * 2] + part[p * 2 + 1] + pb;
        logits_s[p] = lg;
        lm = fmaxf(lm, lg);
    }
#pragma unroll
    for (int o = 16; o > 0; o >>= 1) lm = fmaxf(lm, __shfl_xor_sync(0xffffffffu, lm, o));
    if (lane == 0) rmax[wid] = lm;
    __syncthreads();

    float gmax = rmax[0];
#pragma unroll
    for (int wq = 1; wq < 8; ++wq) gmax = fmaxf(gmax, rmax[wq]);

    float ls = 0.f;
    for (int p = tid; p < NP; p += THREADS) {
        float e = __expf(logits_s[p] - gmax);
        ls += e;
        int rs;
        int i = row_of(p, rs);
        int j = i + 1 + (p - rs);
        float et = __uint_as_float(tf32_of(e));
        Sm[i * SP + j] = et;
        Sm[j * SP + i] = et;
    }
#pragma unroll
    for (int o = 16; o > 0; o >>= 1) ls += __shfl_xor_sync(0xffffffffu, ls, o);
    if (lane == 0) rsum[wid] = ls;
    __syncthreads();

    // ---- Phase 4: Y = S @ X via MMA; warp w handles ntile w (8 dims) ----
    {
        const int w = wid;
        const int nc = w * 8 + qr;
        uint32_t Bx[5][2];
#pragma unroll
        for (int kt = 0; kt < 5; ++kt) {
            const int k0 = kt * 8 + kd * 2;
            Bx[kt][0] = tf32_of(xs[k0 * XP + nc]);
            Bx[kt][1] = tf32_of(xs[(k0 + 1) * XP + nc]);
        }
#pragma unroll
        for (int mt = 0; mt < 3; ++mt) {
            float c0 = 0.f, c1 = 0.f, c2 = 0.f, c3 = 0.f;
            const int row = mt * 16 + qr;
#pragma unroll
            for (int kt = 0; kt < 5; ++kt) {
                const int k0 = kt * 8 + kd * 2;
                const float2 sA = *(const float2*)(Sm + row * SP + k0);       // a0, a2
                const float2 sB = *(const float2*)(Sm + (row + 8) * SP + k0); // a1, a3
                mma8(c0, c1, c2, c3,
                     __float_as_uint(sA.x), __float_as_uint(sB.x),
                     __float_as_uint(sA.y), __float_as_uint(sB.y),
                     Bx[kt][0], Bx[kt][1]);
            }
            *(float2*)(Ym + row * YP + w * 8 + kd * 2) = make_float2(c0, c1);
            if (mt < 2)
                *(float2*)(Ym + (row + 8) * YP + w * 8 + kd * 2) = make_float2(c2, c3);
        }
    }
    __syncthreads();

    // ---- final: attn_out[d] = 0.5 * sum_i x_i[d] * Y[i][d]; dot fc_w; /S ----
    {
        const int d = tid & 63;
        const int q = tid >> 6;
        float pa = 0.f;
#pragma unroll
        for (int i = q * 10; i < q * 10 + 10; ++i)
            pa += xs[i * XP + d] * Ym[i * YP + d];
        p4[q * 64 + d] = pa;
    }
    __syncthreads();

    if (tid < 64) {
        float v = p4[tid] + p4[64 + tid] + p4[128 + tid] + p4[192 + tid];
        red_s[tid] = 0.5f * v * fw_s[tid];
    }
    __syncthreads();

    if (tid == 0) {
        float S = 0.f;
#pragma unroll
        for (int wq = 0; wq < 8; ++wq) S += rsum[wq];
        float tt = 0.f;
#pragma unroll
        for (int k = 0; k < 64; ++k) tt += red_s[k];
        out[b] = tt / S + fc_b[0];
    }
}

extern "C" void kernel_launch(void* const* d_in, const int* in_sizes, int n_in,
                              void* d_out, int out_size)
{
    const float* x      = (const float*)d_in[0];
    const float* attn_w = (const float*)d_in[1];
    const float* attn_b = (const float*)d_in[2];
    const float* proj_w = (const float*)d_in[3];
    const float* proj_b = (const float*)d_in[4];
    const float* fc_w   = (const float*)d_in[5];
    const float* fc_b   = (const float*)d_in[6];
    float* out = (float*)d_out;

    cudaFuncSetAttribute(afm_kernel, cudaFuncAttributeMaxDynamicSharedMemorySize, SMEM_TOTAL);
    afm_kernel<<<2048, THREADS, SMEM_TOTAL>>>(x, attn_w, attn_b, proj_w, proj_b, fc_w, fc_b, out);
}